// round 13
// baseline (speedup 1.0000x reference)
#include <cuda_runtime.h>
#include <cuda_fp16.h>
#include <math.h>
#include <stdint.h>

#define NPTS   32768
#define NE     1024
#define EDIM   256
#define ZSIZE  8388608
#define OUT_ZQ   1
#define OUT_PERP (1 + ZSIZE)
#define OUT_IDX  (2 + ZSIZE)
#define MARGIN   1.0e-3f
#define CAP      16

__device__ float  g_zt[NPTS * EDIM];                 // 32MB transposed z (fp32, exact)
__device__ __half g_wh[NE * EDIM];                   // 512KB fp16 codebook
__device__ __half g_scores_h[(size_t)NPTS * NE];     // 64MB fp16 approx scores
__device__ float  g_min[NPTS];
__device__ int    g_idx[NPTS];
__device__ float  g_enorm[NE];
__device__ int    g_counts[NE];
__device__ float  g_loss_sum;

__device__ __forceinline__ uint32_t encF(float f) {
    uint32_t u = __float_as_uint(f);
    return (u & 0x80000000u) ? ~u : (u | 0x80000000u);
}
__device__ __forceinline__ float decF(uint32_t u) {
    u = (u & 0x80000000u) ? (u & 0x7FFFFFFFu) : ~u;
    return __uint_as_float(u);
}
__device__ __forceinline__ uint32_t pk2h(float a, float b) {
    __half2 h = __floats2half2_rn(a, b);
    return *(uint32_t*)&h;
}

#define MMA_F16(d, a, b) \
    asm volatile("mma.sync.aligned.m16n8k16.row.col.f32.f16.f16.f32 " \
        "{%0,%1,%2,%3}, {%4,%5,%6,%7}, {%8,%9}, {%0,%1,%2,%3};" \
        : "+f"((d)[0]), "+f"((d)[1]), "+f"((d)[2]), "+f"((d)[3]) \
        : "r"((a)[0]), "r"((a)[1]), "r"((a)[2]), "r"((a)[3]), \
          "r"((b)[0]), "r"((b)[1]))

// ======================= transpose: z (B,C,H,W) -> z_t (N, C) fp32 ==================
__global__ __launch_bounds__(256) void transpose_kernel(const float* __restrict__ z) {
    __shared__ float tile[256 * 33];
    int t = threadIdx.x;
    int n0 = blockIdx.x * 32;
    int b = n0 >> 10, hw0 = n0 & 1023;
    const float* zb = z + (size_t)b * 262144 + hw0;
#pragma unroll
    for (int i = 0; i < 8; i++) {
        int idx = t + i * 256;
        int c = idx >> 3, q = idx & 7;
        float4 v = *(const float4*)(zb + (size_t)c * 1024 + q * 4);
        tile[c * 33 + q * 4 + 0] = v.x; tile[c * 33 + q * 4 + 1] = v.y;
        tile[c * 33 + q * 4 + 2] = v.z; tile[c * 33 + q * 4 + 3] = v.w;
    }
    __syncthreads();
#pragma unroll
    for (int i = 0; i < 8; i++) {
        int idx = t + i * 256;
        int m = idx >> 6, c4 = idx & 63;
        float4 o;
        o.x = tile[(c4 * 4 + 0) * 33 + m]; o.y = tile[(c4 * 4 + 1) * 33 + m];
        o.z = tile[(c4 * 4 + 2) * 33 + m]; o.w = tile[(c4 * 4 + 3) * 33 + m];
        *(float4*)(g_zt + (size_t)(n0 + m) * 256 + c4 * 4) = o;
    }
}

// ======================= enorm: exact ||e||^2 + fp16 codebook + zero accum ==========
__global__ void enorm_kernel(const float* __restrict__ w) {
    int c = blockIdx.x * blockDim.x + threadIdx.x;
    g_counts[c] = 0;
    if (c == 0) g_loss_sum = 0.f;
    const float* row = w + (size_t)c * EDIM;
    float s = 0.f;
#pragma unroll 8
    for (int k = 0; k < EDIM; k++) {
        float v = row[k];
        s = __fadd_rn(s, __fmul_rn(v, v));
    }
    g_enorm[c] = s;
    uint32_t* dst = (uint32_t*)(g_wh + (size_t)c * EDIM);
#pragma unroll 8
    for (int k = 0; k < 128; k++)
        dst[k] = pk2h(row[2 * k], row[2 * k + 1]);
}

// ======================= fp16 HMMA GEMM: fp16 scores + per-point min ============
// 512 threads (16 warps 4x4). CTA: 128 points x 1024 codes (8 tiles of 128).
// A (128x256 fp16) smem-resident stride 264. B double-buffered 128x32 halves
// (stride 40) staged from pre-converted g_wh (uint4, no cvt in hot loop).
#define AST2 264
#define BST2 40
#define A_HL (128 * AST2)
#define B_HL (128 * BST2)
#define SMEM_MMA (A_HL * 2 + 2 * B_HL * 2 + 1024 * 4 + 512)

__global__ __launch_bounds__(512, 1)
void mma_kernel(void) {
    extern __shared__ __half smh[];
    __half* A_s = smh;
    __half* B_s = smh + A_HL;                          // [2][B_HL]
    float*  sw_s = (float*)(smh + A_HL + 2 * B_HL);    // [1024]
    uint32_t* smin = (uint32_t*)(sw_s + 1024);         // [128]

    int tid = threadIdx.x;
    int lane = tid & 31, wid = tid >> 5;
    int g = lane >> 2, t = lane & 3;
    int wm = wid >> 2, wn = wid & 3;
    int n0 = blockIdx.x * 128;

    if (tid < 128) smin[tid] = 0xFFFFFFFFu;
    for (int i = tid; i < NE; i += 512) sw_s[i] = g_enorm[i];

    // A fill: 128 x 256 fp32 -> fp16 (once per CTA)
#pragma unroll
    for (int i = 0; i < 16; i++) {
        int idx = tid + i * 512;
        int m = idx >> 6, c4 = (idx & 63) << 2;
        float4 v = *(const float4*)(g_zt + (size_t)(n0 + m) * 256 + c4);
        uint2 h;
        h.x = pk2h(v.x, v.y); h.y = pk2h(v.z, v.w);
        *(uint2*)(A_s + m * AST2 + c4) = h;
    }

    // B staging indices: one uint4 (8 halves) per thread per chunk
    int bc0 = tid >> 2, bq0 = (tid & 3) << 3;

    __half2* hs = (__half2*)g_scores_h;
    float rm[4] = {3.4e38f, 3.4e38f, 3.4e38f, 3.4e38f};

    for (int j = 0; j < 8; j++) {
        float acc[2][4][4];
#pragma unroll
        for (int mt = 0; mt < 2; mt++)
#pragma unroll
            for (int nt = 0; nt < 4; nt++)
#pragma unroll
                for (int q = 0; q < 4; q++) acc[mt][nt][q] = 0.f;

        {   // prologue: B chunk kc=0 -> buf 0
            uint4 v = *(const uint4*)(g_wh + (size_t)(j * 128 + bc0) * 256 + bq0);
            *(uint4*)(B_s + bc0 * BST2 + bq0) = v;
        }
        __syncthreads();

        for (int kc = 0; kc < 8; kc++) {
            int buf = kc & 1;
            uint4 pf;
            if (kc < 7)   // prefetch next chunk into registers
                pf = *(const uint4*)(g_wh + (size_t)(j * 128 + bc0) * 256 + (kc + 1) * 32 + bq0);
            const __half* Bb = B_s + buf * B_HL;
#pragma unroll
            for (int ks = 0; ks < 2; ks++) {
                int koff = ks * 16;
                uint32_t bf[4][2];
#pragma unroll
                for (int nt = 0; nt < 4; nt++) {
                    int code = wn * 32 + nt * 8 + g;
                    bf[nt][0] = *(const uint32_t*)(Bb + code * BST2 + koff + 2 * t);
                    bf[nt][1] = *(const uint32_t*)(Bb + code * BST2 + koff + 2 * t + 8);
                }
#pragma unroll
                for (int mt = 0; mt < 2; mt++) {
                    int row = wm * 32 + mt * 16 + g;
                    int k0 = kc * 32 + koff;
                    uint32_t af[4];
                    af[0] = *(const uint32_t*)(A_s + row * AST2 + k0 + 2 * t);
                    af[1] = *(const uint32_t*)(A_s + (row + 8) * AST2 + k0 + 2 * t);
                    af[2] = *(const uint32_t*)(A_s + row * AST2 + k0 + 2 * t + 8);
                    af[3] = *(const uint32_t*)(A_s + (row + 8) * AST2 + k0 + 2 * t + 8);
#pragma unroll
                    for (int nt = 0; nt < 4; nt++)
                        MMA_F16(acc[mt][nt], af, bf[nt]);
                }
            }
            if (kc < 7)
                *(uint4*)(B_s + (buf ^ 1) * B_HL + bc0 * BST2 + bq0) = pf;
            __syncthreads();
        }

        // epilogue: s = sw - 2*dot, fp16 store, track per-row min
#pragma unroll
        for (int nt = 0; nt < 4; nt++) {
            int colg = j * 128 + wn * 32 + nt * 8 + 2 * t;
            float sw0 = sw_s[colg], sw1 = sw_s[colg + 1];
#pragma unroll
            for (int mt = 0; mt < 2; mt++) {
                int row0 = wm * 32 + mt * 16 + g;
                float s00 = fmaf(-2.f, acc[mt][nt][0], sw0);
                float s01 = fmaf(-2.f, acc[mt][nt][1], sw1);
                float s10 = fmaf(-2.f, acc[mt][nt][2], sw0);
                float s11 = fmaf(-2.f, acc[mt][nt][3], sw1);
                hs[(((size_t)(n0 + row0)) * 1024 + colg) >> 1] = __floats2half2_rn(s00, s01);
                hs[(((size_t)(n0 + row0 + 8)) * 1024 + colg) >> 1] = __floats2half2_rn(s10, s11);
                rm[mt * 2]     = fminf(rm[mt * 2],     fminf(s00, s01));
                rm[mt * 2 + 1] = fminf(rm[mt * 2 + 1], fminf(s10, s11));
            }
        }
    }

#pragma unroll
    for (int r = 0; r < 4; r++) {
        int row = wm * 32 + (r >> 1) * 16 + (r & 1) * 8 + g;
        atomicMin(&smin[row], encF(rm[r]));
    }
    __syncthreads();
    if (tid < 128) g_min[n0 + tid] = decF(smin[tid]);
}

// ======================= rescore: streaming threshold (hmin2 fast path) ========
__global__ __launch_bounds__(256) void rescore_kernel(const float* __restrict__ w,
                                                      float* __restrict__ out) {
    __shared__ float thr_s[32];
    __shared__ int ccnt[32];
    __shared__ int cand[32][CAP];
    __shared__ unsigned long long best[32];
    int tid = threadIdx.x;
    int n0 = blockIdx.x * 32;

    if (tid < 32) {
        thr_s[tid] = g_min[n0 + tid] + MARGIN;
        ccnt[tid] = 0;
        best[tid] = 0xFFFFFFFFFFFFFFFFull;
    }
    __syncthreads();

    // stream 32 rows x 128 uint4; hmin2 tree skips blocks with no candidate
#pragma unroll
    for (int i = 0; i < 16; i++) {
        int idx = tid + i * 256;
        int row = idx >> 7, pos = idx & 127;
        uint4 v = *(const uint4*)(g_scores_h + (size_t)(n0 + row) * 1024 + pos * 8);
        float thr = thr_s[row];
        const __half2* h2 = (const __half2*)&v.x;
        __half2 m = __hmin2(__hmin2(h2[0], h2[1]), __hmin2(h2[2], h2[3]));
        float lm = fminf(__low2float(m), __high2float(m));
        if (lm <= thr) {
            const uint32_t* wd = &v.x;
#pragma unroll
            for (int j = 0; j < 4; j++) {
                float2 f = __half22float2(*(const __half2*)&wd[j]);
                if (f.x <= thr) {
                    int ps = atomicAdd(&ccnt[row], 1);
                    if (ps < CAP) cand[row][ps] = pos * 8 + j * 2;
                }
                if (f.y <= thr) {
                    int ps = atomicAdd(&ccnt[row], 1);
                    if (ps < CAP) cand[row][ps] = pos * 8 + j * 2 + 1;
                }
            }
        }
    }
    __syncthreads();

    // exact rescore: 8 threads per point (bit-exact reference chains)
    {
        int p = tid >> 3, ci0 = tid & 7;
        int cnt = ccnt[p];
        if (cnt > 1) {
            int n = n0 + p;
            const float* zr = g_zt + (size_t)n * 256;
            if (cnt <= CAP) {
                for (int ci = ci0; ci < cnt; ci += 8) {
                    int code = cand[p][ci];
                    const float* wr = w + (size_t)code * EDIM;
                    float szl = 0.f, dot = 0.f;
#pragma unroll 8
                    for (int k = 0; k < EDIM; k++) {
                        float zv = zr[k];
                        szl = __fadd_rn(szl, __fmul_rn(zv, zv));   // exact chain
                        dot = fmaf(zv, wr[k], dot);                // exact chain
                    }
                    float d = __fsub_rn(__fadd_rn(szl, __ldg(&g_enorm[code])),
                                        __fmul_rn(2.f, dot));
                    unsigned long long pk =
                        ((unsigned long long)encF(d) << 32) | (uint32_t)code;
                    atomicMin(&best[p], pk);
                }
            } else {   // overflow fallback (≈never): exact full scan
                for (int code = ci0; code < NE; code += 8) {
                    const float* wr = w + (size_t)code * EDIM;
                    float szl = 0.f, dot = 0.f;
#pragma unroll 8
                    for (int k = 0; k < EDIM; k++) {
                        float zv = zr[k];
                        szl = __fadd_rn(szl, __fmul_rn(zv, zv));
                        dot = fmaf(zv, wr[k], dot);
                    }
                    float d = __fsub_rn(__fadd_rn(szl, __ldg(&g_enorm[code])),
                                        __fmul_rn(2.f, dot));
                    unsigned long long pk =
                        ((unsigned long long)encF(d) << 32) | (uint32_t)code;
                    atomicMin(&best[p], pk);
                }
            }
        }
    }
    __syncthreads();
    if (tid < 32) {
        int cnt = ccnt[tid];
        int bc = (cnt == 1) ? cand[tid][0] : (int)(best[tid] & 0xFFFFFFFFu);
        g_idx[n0 + tid] = bc;
        out[OUT_IDX + n0 + tid] = (float)bc;
        atomicAdd(&g_counts[bc], 1);
    }
}

// ======================= gather: z_q_out (STE) + loss =======================
__global__ __launch_bounds__(256) void gather_kernel(const float* __restrict__ z,
                                                     const float* __restrict__ w,
                                                     float* __restrict__ out) {
    __shared__ float wrow[32][257];
    __shared__ int ids[32];
    __shared__ float red[8];
    int t = threadIdx.x, lane = t & 31, wrp = t >> 5;
    int n0 = blockIdx.x * 32;
    int b = n0 >> 10, hw0 = n0 & 1023;

    if (t < 32) ids[t] = g_idx[n0 + t];
    __syncthreads();
#pragma unroll
    for (int i = 0; i < 8; i++) {
        int idx = t + i * 256;
        int r = idx >> 6, q = idx & 63;
        float4 v = *(const float4*)(w + (size_t)ids[r] * 256 + q * 4);
        wrow[r][q * 4 + 0] = v.x; wrow[r][q * 4 + 1] = v.y;
        wrow[r][q * 4 + 2] = v.z; wrow[r][q * 4 + 3] = v.w;
    }
    __syncthreads();

    float loss = 0.f;
    const float* zb = z + (size_t)b * 262144 + hw0;
    float* ob = out + OUT_ZQ + (size_t)b * 262144 + hw0;
    for (int c = wrp; c < 256; c += 8) {
        float zv = zb[(size_t)c * 1024 + lane];
        float q = wrow[lane][c];
        float d = __fsub_rn(q, zv);
        ob[(size_t)c * 1024 + lane] = __fadd_rn(zv, d);
        loss += d * d;
    }
#pragma unroll
    for (int off = 16; off; off >>= 1) loss += __shfl_down_sync(0xffffffffu, loss, off);
    if (lane == 0) red[wrp] = loss;
    __syncthreads();
    if (wrp == 0) {
        float v = (lane < 8) ? red[lane] : 0.f;
#pragma unroll
        for (int off = 4; off; off >>= 1) v += __shfl_down_sync(0xffffffffu, v, off);
        if (lane == 0) atomicAdd(&g_loss_sum, v);
    }
}

// ======================= finalize =======================
__global__ void finalize_kernel(float* __restrict__ out) {
    int t = threadIdx.x;
    float em = (float)g_counts[t] * (1.0f / 32768.f);
    float s = em * logf(em + 1e-10f);
#pragma unroll
    for (int off = 16; off; off >>= 1) s += __shfl_down_sync(0xffffffffu, s, off);
    __shared__ float red[32];
    int lane = t & 31, wid = t >> 5;
    if (lane == 0) red[wid] = s;
    __syncthreads();
    if (wid == 0) {
        float v = red[lane];
#pragma unroll
        for (int off = 16; off; off >>= 1) v += __shfl_down_sync(0xffffffffu, v, off);
        if (lane == 0) {
            out[0] = g_loss_sum * (1.25f / 8388608.f);
            out[OUT_PERP] = expf(-v);
        }
    }
}

// ======================= launch =======================
extern "C" void kernel_launch(void* const* d_in, const int* in_sizes, int n_in,
                              void* d_out, int out_size) {
    const float* z = (const float*)d_in[0];
    const float* w = (const float*)d_in[1];
    float* out = (float*)d_out;

    cudaFuncSetAttribute(mma_kernel, cudaFuncAttributeMaxDynamicSharedMemorySize, SMEM_MMA);

    transpose_kernel<<<NPTS / 32, 256>>>(z);
    enorm_kernel<<<4, 256>>>(w);
    mma_kernel<<<NPTS / 128, 512, SMEM_MMA>>>();
    rescore_kernel<<<NPTS / 32, 256>>>(w, out);
    gather_kernel<<<NPTS / 32, 256>>>(z, w, out);
    finalize_kernel<<<1, 1024>>>(out);
}

// round 14
// speedup vs baseline: 1.3319x; 1.3319x over previous
#include <cuda_runtime.h>
#include <cuda_fp16.h>
#include <math.h>
#include <stdint.h>

#define NPTS   32768
#define NE     1024
#define EDIM   256
#define ZSIZE  8388608
#define OUT_ZQ   1
#define OUT_PERP (1 + ZSIZE)
#define OUT_IDX  (2 + ZSIZE)
#define MARGIN   1.0e-3f
#define CAP      16

__device__ float  g_zt[NPTS * EDIM];                 // 32MB transposed z
__device__ __half g_scores_h[(size_t)NPTS * NE];     // 64MB fp16 approx scores
__device__ float  g_min[NPTS];
__device__ int    g_idx[NPTS];
__device__ float  g_enorm[NE];
__device__ int    g_counts[NE];
__device__ float  g_loss_sum;

__device__ __forceinline__ uint32_t encF(float f) {
    uint32_t u = __float_as_uint(f);
    return (u & 0x80000000u) ? ~u : (u | 0x80000000u);
}
__device__ __forceinline__ float decF(uint32_t u) {
    u = (u & 0x80000000u) ? (u & 0x7FFFFFFFu) : ~u;
    return __uint_as_float(u);
}
__device__ __forceinline__ uint32_t pk2h(float a, float b) {
    __half2 h = __floats2half2_rn(a, b);
    return *(uint32_t*)&h;
}

#define MMA_F16(d, a, b) \
    asm volatile("mma.sync.aligned.m16n8k16.row.col.f32.f16.f16.f32 " \
        "{%0,%1,%2,%3}, {%4,%5,%6,%7}, {%8,%9}, {%0,%1,%2,%3};" \
        : "+f"((d)[0]), "+f"((d)[1]), "+f"((d)[2]), "+f"((d)[3]) \
        : "r"((a)[0]), "r"((a)[1]), "r"((a)[2]), "r"((a)[3]), \
          "r"((b)[0]), "r"((b)[1]))

#define LDSM_X4(r0, r1, r2, r3, addr) \
    asm volatile("ldmatrix.sync.aligned.m8n8.x4.shared.b16 {%0,%1,%2,%3}, [%4];" \
        : "=r"(r0), "=r"(r1), "=r"(r2), "=r"(r3) : "r"(addr))

// ======================= transpose: z (B,C,H,W) -> z_t (N, C) =======================
__global__ __launch_bounds__(256) void transpose_kernel(const float* __restrict__ z) {
    __shared__ float tile[256 * 33];
    int t = threadIdx.x;
    int n0 = blockIdx.x * 32;
    int b = n0 >> 10, hw0 = n0 & 1023;
    const float* zb = z + (size_t)b * 262144 + hw0;
#pragma unroll
    for (int i = 0; i < 8; i++) {
        int idx = t + i * 256;
        int c = idx >> 3, q = idx & 7;
        float4 v = *(const float4*)(zb + (size_t)c * 1024 + q * 4);
        tile[c * 33 + q * 4 + 0] = v.x; tile[c * 33 + q * 4 + 1] = v.y;
        tile[c * 33 + q * 4 + 2] = v.z; tile[c * 33 + q * 4 + 3] = v.w;
    }
    __syncthreads();
#pragma unroll
    for (int i = 0; i < 8; i++) {
        int idx = t + i * 256;
        int m = idx >> 6, c4 = idx & 63;
        float4 o;
        o.x = tile[(c4 * 4 + 0) * 33 + m]; o.y = tile[(c4 * 4 + 1) * 33 + m];
        o.z = tile[(c4 * 4 + 2) * 33 + m]; o.w = tile[(c4 * 4 + 3) * 33 + m];
        *(float4*)(g_zt + (size_t)(n0 + m) * 256 + c4 * 4) = o;
    }
}

// ======================= enorm: exact ||e||^2 + zero accumulators =======================
__global__ void enorm_kernel(const float* __restrict__ w) {
    int c = blockIdx.x * blockDim.x + threadIdx.x;
    g_counts[c] = 0;
    if (c == 0) g_loss_sum = 0.f;
    const float* row = w + (size_t)c * EDIM;
    float s = 0.f;
#pragma unroll 8
    for (int k = 0; k < EDIM; k++) {
        float v = row[k];
        s = __fadd_rn(s, __fmul_rn(v, v));
    }
    g_enorm[c] = s;
}

// ======================= fp16 HMMA GEMM: fp16 scores + per-point min ============
// R9 structure exactly; only fragment loads switched to ldmatrix.x4.
#define AST2 264
#define BST2 40
#define A_HL (128 * AST2)
#define B_HL (128 * BST2)
#define SMEM_MMA (A_HL * 2 + 2 * B_HL * 2 + 1024 * 4 + 512)

__global__ __launch_bounds__(512, 1)
void mma_kernel(const float* __restrict__ w) {
    extern __shared__ __half smh[];
    __half* A_s = smh;
    __half* B_s = smh + A_HL;                          // [2][B_HL]
    float*  sw_s = (float*)(smh + A_HL + 2 * B_HL);    // [1024]
    uint32_t* smin = (uint32_t*)(sw_s + 1024);         // [128]

    int tid = threadIdx.x;
    int lane = tid & 31, wid = tid >> 5;
    int g = lane >> 2, t = lane & 3;
    int wm = wid >> 2, wn = wid & 3;
    int n0 = blockIdx.x * 128;

    if (tid < 128) smin[tid] = 0xFFFFFFFFu;
    for (int i = tid; i < NE; i += 512) sw_s[i] = g_enorm[i];

    // A fill: 128 x 256 fp32 -> fp16
#pragma unroll
    for (int i = 0; i < 16; i++) {
        int idx = tid + i * 512;
        int m = idx >> 6, c4 = (idx & 63) << 2;
        float4 v = *(const float4*)(g_zt + (size_t)(n0 + m) * 256 + c4);
        uint2 h;
        h.x = pk2h(v.x, v.y); h.y = pk2h(v.z, v.w);
        *(uint2*)(A_s + m * AST2 + c4) = h;
    }

    int c0 = tid >> 3, kq0 = (tid & 7) << 2;
    int c1 = (tid + 512) >> 3, kq1 = ((tid + 512) & 7) << 2;

    uint32_t A_b = (uint32_t)__cvta_generic_to_shared(A_s);
    uint32_t B_b = (uint32_t)__cvta_generic_to_shared(B_s);

    __half2* hs = (__half2*)g_scores_h;
    float rm[4] = {3.4e38f, 3.4e38f, 3.4e38f, 3.4e38f};

    for (int j = 0; j < 8; j++) {
        float acc[2][4][4];
#pragma unroll
        for (int mt = 0; mt < 2; mt++)
#pragma unroll
            for (int nt = 0; nt < 4; nt++)
#pragma unroll
                for (int q = 0; q < 4; q++) acc[mt][nt][q] = 0.f;

        {   // prologue: B chunk kc=0 -> buf 0
            const float* wp = w + (size_t)(j * 128) * 256;
            float4 v0 = *(const float4*)(wp + (size_t)c0 * 256 + kq0);
            float4 v1 = *(const float4*)(wp + (size_t)c1 * 256 + kq1);
            uint2 h0, h1;
            h0.x = pk2h(v0.x, v0.y); h0.y = pk2h(v0.z, v0.w);
            h1.x = pk2h(v1.x, v1.y); h1.y = pk2h(v1.z, v1.w);
            *(uint2*)(B_s + c0 * BST2 + kq0) = h0;
            *(uint2*)(B_s + c1 * BST2 + kq1) = h1;
        }
        __syncthreads();

        for (int kc = 0; kc < 8; kc++) {
            int buf = kc & 1;
            float4 pf0, pf1;
            if (kc < 7) {
                const float* wp = w + (size_t)(j * 128) * 256 + (kc + 1) * 32;
                pf0 = *(const float4*)(wp + (size_t)c0 * 256 + kq0);
                pf1 = *(const float4*)(wp + (size_t)c1 * 256 + kq1);
            }
            uint32_t Bb = B_b + buf * B_HL * 2;
#pragma unroll
            for (int ks = 0; ks < 2; ks++) {
                int koff = ks * 16;
                uint32_t bf[4][2];
                int brow = wn * 32 + ((lane >> 4) & 1) * 8 + (lane & 7);
                int bcol = koff + ((lane >> 3) & 1) * 8;
                LDSM_X4(bf[0][0], bf[0][1], bf[1][0], bf[1][1],
                        Bb + (brow * BST2 + bcol) * 2);
                LDSM_X4(bf[2][0], bf[2][1], bf[3][0], bf[3][1],
                        Bb + ((brow + 16) * BST2 + bcol) * 2);
#pragma unroll
                for (int mt = 0; mt < 2; mt++) {
                    int arow = wm * 32 + mt * 16 + (lane & 15);
                    int acol = kc * 32 + koff + ((lane >> 4) << 3);
                    uint32_t af[4];
                    LDSM_X4(af[0], af[1], af[2], af[3],
                            A_b + (arow * AST2 + acol) * 2);
#pragma unroll
                    for (int nt = 0; nt < 4; nt++)
                        MMA_F16(acc[mt][nt], af, bf[nt]);
                }
            }
            if (kc < 7) {
                uint2 h0, h1;
                h0.x = pk2h(pf0.x, pf0.y); h0.y = pk2h(pf0.z, pf0.w);
                h1.x = pk2h(pf1.x, pf1.y); h1.y = pk2h(pf1.z, pf1.w);
                *(uint2*)(B_s + (buf ^ 1) * B_HL + c0 * BST2 + kq0) = h0;
                *(uint2*)(B_s + (buf ^ 1) * B_HL + c1 * BST2 + kq1) = h1;
            }
            __syncthreads();
        }

        // epilogue: s = sw - 2*dot, fp16 store, track per-row min
#pragma unroll
        for (int nt = 0; nt < 4; nt++) {
            int colg = j * 128 + wn * 32 + nt * 8 + 2 * t;
            float sw0 = sw_s[colg], sw1 = sw_s[colg + 1];
#pragma unroll
            for (int mt = 0; mt < 2; mt++) {
                int row0 = wm * 32 + mt * 16 + g;
                float s00 = fmaf(-2.f, acc[mt][nt][0], sw0);
                float s01 = fmaf(-2.f, acc[mt][nt][1], sw1);
                float s10 = fmaf(-2.f, acc[mt][nt][2], sw0);
                float s11 = fmaf(-2.f, acc[mt][nt][3], sw1);
                hs[(((size_t)(n0 + row0)) * 1024 + colg) >> 1] = __floats2half2_rn(s00, s01);
                hs[(((size_t)(n0 + row0 + 8)) * 1024 + colg) >> 1] = __floats2half2_rn(s10, s11);
                rm[mt * 2]     = fminf(rm[mt * 2],     fminf(s00, s01));
                rm[mt * 2 + 1] = fminf(rm[mt * 2 + 1], fminf(s10, s11));
            }
        }
    }

#pragma unroll
    for (int r = 0; r < 4; r++) {
        int row = wm * 32 + (r >> 1) * 16 + (r & 1) * 8 + g;
        atomicMin(&smin[row], encF(rm[r]));
    }
    __syncthreads();
    if (tid < 128) g_min[n0 + tid] = decF(smin[tid]);
}

// ======================= rescore: streaming threshold + exact rescore ========
__global__ __launch_bounds__(256) void rescore_kernel(const float* __restrict__ w,
                                                      float* __restrict__ out) {
    __shared__ float thr_s[32];
    __shared__ int ccnt[32];
    __shared__ int cand[32][CAP];
    __shared__ unsigned long long best[32];
    int tid = threadIdx.x;
    int n0 = blockIdx.x * 32;

    if (tid < 32) {
        thr_s[tid] = g_min[n0 + tid] + MARGIN;
        ccnt[tid] = 0;
        best[tid] = 0xFFFFFFFFFFFFFFFFull;
    }
    __syncthreads();

#pragma unroll
    for (int i = 0; i < 16; i++) {
        int idx = tid + i * 256;
        int row = idx >> 7, pos = idx & 127;
        uint4 v = *(const uint4*)(g_scores_h + (size_t)(n0 + row) * 1024 + pos * 8);
        float thr = thr_s[row];
        const uint32_t* wd = &v.x;
#pragma unroll
        for (int j = 0; j < 4; j++) {
            float2 f = __half22float2(*(const __half2*)&wd[j]);
            if (f.x <= thr) {
                int ps = atomicAdd(&ccnt[row], 1);
                if (ps < CAP) cand[row][ps] = pos * 8 + j * 2;
            }
            if (f.y <= thr) {
                int ps = atomicAdd(&ccnt[row], 1);
                if (ps < CAP) cand[row][ps] = pos * 8 + j * 2 + 1;
            }
        }
    }
    __syncthreads();

    {
        int p = tid >> 3, ci0 = tid & 7;
        int cnt = ccnt[p];
        if (cnt > 1) {
            int n = n0 + p;
            const float* zr = g_zt + (size_t)n * 256;
            if (cnt <= CAP) {
                for (int ci = ci0; ci < cnt; ci += 8) {
                    int code = cand[p][ci];
                    const float* wr = w + (size_t)code * EDIM;
                    float szl = 0.f, dot = 0.f;
#pragma unroll 8
                    for (int k = 0; k < EDIM; k++) {
                        float zv = zr[k];
                        szl = __fadd_rn(szl, __fmul_rn(zv, zv));   // exact chain
                        dot = fmaf(zv, wr[k], dot);                // exact chain
                    }
                    float d = __fsub_rn(__fadd_rn(szl, __ldg(&g_enorm[code])),
                                        __fmul_rn(2.f, dot));
                    unsigned long long pk =
                        ((unsigned long long)encF(d) << 32) | (uint32_t)code;
                    atomicMin(&best[p], pk);
                }
            } else {   // overflow fallback: exact full scan
                for (int code = ci0; code < NE; code += 8) {
                    const float* wr = w + (size_t)code * EDIM;
                    float szl = 0.f, dot = 0.f;
#pragma unroll 8
                    for (int k = 0; k < EDIM; k++) {
                        float zv = zr[k];
                        szl = __fadd_rn(szl, __fmul_rn(zv, zv));
                        dot = fmaf(zv, wr[k], dot);
                    }
                    float d = __fsub_rn(__fadd_rn(szl, __ldg(&g_enorm[code])),
                                        __fmul_rn(2.f, dot));
                    unsigned long long pk =
                        ((unsigned long long)encF(d) << 32) | (uint32_t)code;
                    atomicMin(&best[p], pk);
                }
            }
        }
    }
    __syncthreads();
    if (tid < 32) {
        int cnt = ccnt[tid];
        int bc = (cnt == 1) ? cand[tid][0] : (int)(best[tid] & 0xFFFFFFFFu);
        g_idx[n0 + tid] = bc;
        out[OUT_IDX + n0 + tid] = (float)bc;
        atomicAdd(&g_counts[bc], 1);
    }
}

// ======================= gather: z_q_out (STE) + loss =======================
__global__ __launch_bounds__(256) void gather_kernel(const float* __restrict__ z,
                                                     const float* __restrict__ w,
                                                     float* __restrict__ out) {
    __shared__ float wrow[32][257];
    __shared__ int ids[32];
    __shared__ float red[8];
    int t = threadIdx.x, lane = t & 31, wrp = t >> 5;
    int n0 = blockIdx.x * 32;
    int b = n0 >> 10, hw0 = n0 & 1023;

    if (t < 32) ids[t] = g_idx[n0 + t];
    __syncthreads();
#pragma unroll
    for (int i = 0; i < 8; i++) {
        int idx = t + i * 256;
        int r = idx >> 6, q = idx & 63;
        float4 v = *(const float4*)(w + (size_t)ids[r] * 256 + q * 4);
        wrow[r][q * 4 + 0] = v.x; wrow[r][q * 4 + 1] = v.y;
        wrow[r][q * 4 + 2] = v.z; wrow[r][q * 4 + 3] = v.w;
    }
    __syncthreads();

    float loss = 0.f;
    const float* zb = z + (size_t)b * 262144 + hw0;
    float* ob = out + OUT_ZQ + (size_t)b * 262144 + hw0;
    for (int c = wrp; c < 256; c += 8) {
        float zv = zb[(size_t)c * 1024 + lane];
        float q = wrow[lane][c];
        float d = __fsub_rn(q, zv);
        ob[(size_t)c * 1024 + lane] = __fadd_rn(zv, d);
        loss += d * d;
    }
#pragma unroll
    for (int off = 16; off; off >>= 1) loss += __shfl_down_sync(0xffffffffu, loss, off);
    if (lane == 0) red[wrp] = loss;
    __syncthreads();
    if (wrp == 0) {
        float v = (lane < 8) ? red[lane] : 0.f;
#pragma unroll
        for (int off = 4; off; off >>= 1) v += __shfl_down_sync(0xffffffffu, v, off);
        if (lane == 0) atomicAdd(&g_loss_sum, v);
    }
}

// ======================= finalize =======================
__global__ void finalize_kernel(float* __restrict__ out) {
    int t = threadIdx.x;
    float em = (float)g_counts[t] * (1.0f / 32768.f);
    float s = em * logf(em + 1e-10f);
#pragma unroll
    for (int off = 16; off; off >>= 1) s += __shfl_down_sync(0xffffffffu, s, off);
    __shared__ float red[32];
    int lane = t & 31, wid = t >> 5;
    if (lane == 0) red[wid] = s;
    __syncthreads();
    if (wid == 0) {
        float v = red[lane];
#pragma unroll
        for (int off = 16; off; off >>= 1) v += __shfl_down_sync(0xffffffffu, v, off);
        if (lane == 0) {
            out[0] = g_loss_sum * (1.25f / 8388608.f);
            out[OUT_PERP] = expf(-v);
        }
    }
}

// ======================= launch =======================
extern "C" void kernel_launch(void* const* d_in, const int* in_sizes, int n_in,
                              void* d_out, int out_size) {
    const float* z = (const float*)d_in[0];
    const float* w = (const float*)d_in[1];
    float* out = (float*)d_out;

    cudaFuncSetAttribute(mma_kernel, cudaFuncAttributeMaxDynamicSharedMemorySize, SMEM_MMA);

    transpose_kernel<<<NPTS / 32, 256>>>(z);
    enorm_kernel<<<4, 256>>>(w);
    mma_kernel<<<NPTS / 128, 512, SMEM_MMA>>>(w);
    rescore_kernel<<<NPTS / 32, 256>>>(w, out);
    gather_kernel<<<NPTS / 32, 256>>>(z, w, out);
    finalize_kernel<<<1, 1024>>>(out);
}